// round 15
// baseline (speedup 1.0000x reference)
#include <cuda_runtime.h>
#include <math.h>

#define Bb 8
#define Cc 128
#define Nn 65536
#define Ll 64
#define NPT 1024                  // point blocks (512 pts each)
#define NCHH (Bb * Cc * 2)        // 2048 channel half-blocks

// Scratch in device globals. g_censum zeroed by kprep then atomically
// accumulated (exactly 2 adds per cell -> commutative -> deterministic).
__device__ unsigned int g_lab8[Bb * Nn / 4];     // packed uint8 labels
__device__ float g_censum[Bb * Ll * Cc];
__device__ float g_vpart[NPT * Ll];
__device__ float g_cpart[NPT * Ll];

// Low-priority stream for the trickle-in point pass + fork/join events.
// Created once at load (no device memory allocation involved).
static cudaStream_t g_s2;
static cudaEvent_t g_evFork, g_evJoin;
struct _StreamInit {
    _StreamInit() {
        int leastP = 0, greatestP = 0;
        cudaDeviceGetStreamPriorityRange(&leastP, &greatestP);
        cudaStreamCreateWithPriority(&g_s2, cudaStreamNonBlocking, leastP);
        cudaEventCreateWithFlags(&g_evFork, cudaEventDisableTiming);
        cudaEventCreateWithFlags(&g_evJoin, cudaEventDisableTiming);
    }
};
static _StreamInit _stream_init;

// float4/float2 loads with L2 evict-last via cache-policy hint: pred lines
// are touched exactly twice (point + channel pass); retention makes the 2nd
// touch an L2 hit (measured R13: DRAM traffic ~274MB ~= single read).
__device__ __forceinline__ float4 ldg_el(const float4* p) {
    float4 v;
    unsigned long long pol;
    asm volatile("createpolicy.fractional.L2::evict_last.b64 %0, 1.0;" : "=l"(pol));
    asm volatile("ld.global.nc.L2::cache_hint.v4.f32 {%0,%1,%2,%3}, [%4], %5;"
                 : "=f"(v.x), "=f"(v.y), "=f"(v.z), "=f"(v.w)
                 : "l"(p), "l"(pol));
    return v;
}
__device__ __forceinline__ float2 ldg_el2(const float2* p) {
    float2 v;
    unsigned long long pol;
    asm volatile("createpolicy.fractional.L2::evict_last.b64 %0, 1.0;" : "=l"(pol));
    asm volatile("ld.global.nc.L2::cache_hint.v2.f32 {%0,%1}, [%2], %3;"
                 : "=f"(v.x), "=f"(v.y) : "l"(p), "l"(pol));
    return v;
}

// ---------------------------------------------------------------------------
// kprep: pack labels to uint8x4, zero censum + out, prefetch 16MB of pred.
// ---------------------------------------------------------------------------
__global__ __launch_bounds__(256) void kprep(const int* __restrict__ label,
                                             const float* __restrict__ pred,
                                             float* __restrict__ out, int out_size) {
    const int t = blockIdx.x * 256 + threadIdx.x;      // 65536 threads
    const int4* l4 = (const int4*)label;
#pragma unroll
    for (int k = 0; k < 2; k++) {
        int i = t * 2 + k;
        int4 l = l4[i];
        g_lab8[i] = (unsigned)l.x | ((unsigned)l.y << 8) |
                    ((unsigned)l.z << 16) | ((unsigned)l.w << 24);
    }
    g_censum[t] = 0.0f;
    if (t < out_size) out[t] = 0.0f;
    asm volatile("prefetch.global.L2 [%0];" :: "l"(pred + (size_t)t * 64));
}

// ---------------------------------------------------------------------------
// kchan: channel half-pass (32768 pts/block), private-column smem
// accumulator, 3 blocks/SM. Launched FIRST — defines backbone occupancy.
// ---------------------------------------------------------------------------
__global__ __launch_bounds__(256, 3) void kchan(const float* __restrict__ pred) {
    extern __shared__ float sm[];
    const int t = threadIdx.x;
    const int id = blockIdx.x;                          // 0..2047
    const int b = id >> 8;
    const int rem = id & 255;
    const int c = rem >> 1, half = rem & 1;
    float* acc = sm;             // [2 copies][64 labels][128 slots]
    float* red = sm + 16384;     // [256]

    {   // float4 zeroing
        float4* az = (float4*)acc;
        float4 z = make_float4(0.f, 0.f, 0.f, 0.f);
#pragma unroll
        for (int i = 0; i < 16; i++) az[i * 256 + t] = z;
    }
    __syncthreads();

    const float4* p4 = (const float4*)(pred + (size_t)b * Cc * Nn + (size_t)c * Nn)
                       + half * 8192;
    const unsigned* lp = g_lab8 + b * (Nn / 4) + half * 8192;
    float* ap = acc + (t >> 7) * 8192 + (t & 127);      // private slot column

    float4 XA[4], XB[4]; unsigned LA[4], LB[4];
#pragma unroll
    for (int k = 0; k < 4; k++) { XA[k] = ldg_el(p4 + k * 256 + t); LA[k] = lp[k * 256 + t]; }

#pragma unroll 1
    for (int s = 0; s < 8; s += 2) {                    // 8192 float4 total
#pragma unroll
        for (int k = 0; k < 4; k++) {
            int idx = ((s + 1) * 4 + k) * 256 + t;
            XB[k] = ldg_el(p4 + idx); LB[k] = lp[idx];
        }
#pragma unroll
        for (int k = 0; k < 4; k++) {
            ap[(LA[k] & 255) * 128]         += XA[k].x;  // bank=slot%32: clean
            ap[((LA[k] >> 8) & 255) * 128]  += XA[k].y;
            ap[((LA[k] >> 16) & 255) * 128] += XA[k].z;
            ap[(LA[k] >> 24) * 128]         += XA[k].w;
        }
        if (s + 2 < 8) {
#pragma unroll
            for (int k = 0; k < 4; k++) {
                int idx = ((s + 2) * 4 + k) * 256 + t;
                XA[k] = ldg_el(p4 + idx); LA[k] = lp[idx];
            }
        }
#pragma unroll
        for (int k = 0; k < 4; k++) {
            ap[(LB[k] & 255) * 128]         += XB[k].x;
            ap[((LB[k] >> 8) & 255) * 128]  += XB[k].y;
            ap[((LB[k] >> 16) & 255) * 128] += XB[k].z;
            ap[(LB[k] >> 24) * 128]         += XB[k].w;
        }
    }
    __syncthreads();

    {   // float4 diagonal reduce
        const int l = t & 63, q = t >> 6;
        const float4* a4 = (const float4*)acc;
        float s = 0.f;
#pragma unroll
        for (int jj = 0; jj < 8; jj++) {
            int j4 = (q * 8 + jj + l) & 31;
            float4 v0 = a4[l * 32 + j4];
            float4 v1 = a4[2048 + l * 32 + j4];
            s += (v0.x + v0.y + v0.z + v0.w) + (v1.x + v1.y + v1.z + v1.w);
        }
        red[t] = s;
    }
    __syncthreads();
    if (t < Ll)                    // 2 adds/cell: commutative -> deterministic
        atomicAdd(&g_censum[((size_t)b * Ll + t) * Cc + c],
                  red[t] + red[t + 64] + red[t + 128] + red[t + 192]);
}

// ---------------------------------------------------------------------------
// kpoint: per-point pass, tiny smem + low regs; launched SECOND on a low-
// priority stream so its blocks trickle into the one leftover slot per SM,
// pacing batch-aligned alongside kchan (preserves L2 reuse window).
// ---------------------------------------------------------------------------
__global__ __launch_bounds__(256) void kpoint(const float* __restrict__ pred) {
    __shared__ float vbin[Ll];
    __shared__ float cbin[Ll];
    const int t = threadIdx.x;
    const int g = blockIdx.x;                           // 0..1023
    const int b = g >> 7, ps = g & 127;
    const int n0 = ps * 512;                            // 256 thr x 2 pts
    const float2* p2 = (const float2*)(pred + (size_t)b * Cc * Nn + n0);

    float s1x = 0.f, s1y = 0.f, s2x = 0.f, s2y = 0.f;
    float2 VA[8], VB[8];
#pragma unroll
    for (int k = 0; k < 8; k++) VA[k] = ldg_el2(p2 + (size_t)k * (Nn / 2) + t);

#pragma unroll 1
    for (int cg = 0; cg < 16; cg += 2) {
#pragma unroll
        for (int k = 0; k < 8; k++)
            VB[k] = ldg_el2(p2 + (size_t)((cg + 1) * 8 + k) * (Nn / 2) + t);
#pragma unroll
        for (int k = 0; k < 8; k++) {
            s1x += VA[k].x; s2x = fmaf(VA[k].x, VA[k].x, s2x);
            s1y += VA[k].y; s2y = fmaf(VA[k].y, VA[k].y, s2y);
        }
        if (cg + 2 < 16) {
#pragma unroll
            for (int k = 0; k < 8; k++)
                VA[k] = ldg_el2(p2 + (size_t)((cg + 2) * 8 + k) * (Nn / 2) + t);
        }
#pragma unroll
        for (int k = 0; k < 8; k++) {
            s1x += VB[k].x; s2x = fmaf(VB[k].x, VB[k].x, s2x);
            s1y += VB[k].y; s2y = fmaf(VB[k].y, VB[k].y, s2y);
        }
    }
    unsigned w = g_lab8[b * (Nn / 4) + (n0 >> 2) + (t >> 1)];
    int sh = (t & 1) * 16;
    int l0 = (w >> sh) & 255, l1 = (w >> (sh + 8)) & 255;

    if (t < Ll) { vbin[t] = 0.f; cbin[t] = 0.f; }
    __syncthreads();
    {
        float pn2, d, v;
        pn2 = fmaxf(s2x - s1x * s1x * (1.0f / Cc), 0.f);
        d = sqrtf(pn2) - 0.5f; v = (d > 0.f) ? d * d : 0.f;
        atomicAdd(&vbin[l0], v); atomicAdd(&cbin[l0], 1.f);
        pn2 = fmaxf(s2y - s1y * s1y * (1.0f / Cc), 0.f);
        d = sqrtf(pn2) - 0.5f; v = (d > 0.f) ? d * d : 0.f;
        atomicAdd(&vbin[l1], v); atomicAdd(&cbin[l1], 1.f);
    }
    __syncthreads();
    if (t < Ll) {
        g_vpart[g * Ll + t] = vbin[t];
        g_cpart[g * Ll + t] = cbin[t];
    }
}

// ---------------------------------------------------------------------------
// kfin: merged finalize. Grid (32, Bb); block q covers d in [q*4, q*4+4).
// ---------------------------------------------------------------------------
__global__ __launch_bounds__(256) void kfin(float* __restrict__ out) {
    const int q = blockIdx.x, b = blockIdx.y, t = threadIdx.x;
    __shared__ float cen[Ll][Cc];    // 32 KB
    __shared__ float ps[256];
    __shared__ float qs[256];
    __shared__ float icnt[Ll];
    __shared__ float vc[Ll];
    __shared__ float sq[Cc];
    __shared__ float red[8];

    {   // counts + vsums: 32 point-blocks per thread (128 per batch)
        const int l = t & 63, sg = t >> 6;
        float cs = 0.f, vv = 0.f;
#pragma unroll 4
        for (int k = 0; k < 32; k++) {
            int idx = (b * 128 + sg * 32 + k) * Ll + l;
            cs += g_cpart[idx];
            vv += g_vpart[idx];
        }
        ps[t] = cs; qs[t] = vv;
    }
    __syncthreads();
    if (t < Ll) {
        float ctot = ps[t] + ps[t + 64] + ps[t + 128] + ps[t + 192];
        icnt[t] = 1.0f / ctot;
        vc[t] = (qs[t] + qs[t + 64] + qs[t + 128] + qs[t + 192]) / ctot;
    }
    __syncthreads();

    {   // normalized centers
        const float4* src = (const float4*)(g_censum + (size_t)b * Ll * Cc);
        float4* dst = (float4*)&cen[0][0];
#pragma unroll
        for (int i = 0; i < 8; i++) {
            int idx = i * 256 + t;
            float ic = icnt[idx >> 5];
            float4 v = src[idx];
            v.x *= ic; v.y *= ic; v.z *= ic; v.w *= ic;
            dst[idx] = v;
        }
    }
    __syncthreads();

    {   // sqn
        const int c = t & 127, h = t >> 7;
        float s = 0.f;
#pragma unroll 8
        for (int l = h * 32; l < h * 32 + 32; l++) { float v = cen[l][c]; s = fmaf(v, v, s); }
        ps[t] = s;
    }
    __syncthreads();
    if (t < Cc) sq[t] = ps[t] + ps[t + 128];
    __syncthreads();

    const int cc = t & 127;
    const int d0 = q * 4 + (t >> 7) * 2;
    float g0 = 0.f, g1 = 0.f;
#pragma unroll 8
    for (int l = 0; l < Ll; l++) {
        float a = cen[l][cc];
        g0 = fmaf(a, cen[l][d0 + 0], g0);
        g1 = fmaf(a, cen[l][d0 + 1], g1);
    }
    float local = 0.f;
#pragma unroll
    for (int j = 0; j < 2; j++) {
        float gg = j ? g1 : g0;
        float sqd = fmaxf(sq[cc] + sq[d0 + j] - 2.0f * gg, 0.f);
        float dist = (sqd > 0.f) ? sqrtf(sqd) : 0.f;
        float h = fmaxf(3.0f - dist, 0.f);        // 2*D_DIST
        local = fmaf(h, h, local);
    }
    local *= (1.0f / 8064.0f);                    // P_DIST / (2*L*(L-1))

    if (q == 0 && t < Cc) {
        local += 0.001f * sqrtf(sq[t]) * (1.0f / 64.0f);   // l_reg
        if (t < Ll) local += vc[t] * (1.0f / 64.0f);       // var
    }

    for (int off = 16; off > 0; off >>= 1)
        local += __shfl_down_sync(0xFFFFFFFFu, local, off);
    if ((t & 31) == 0) red[t >> 5] = local;
    __syncthreads();
    if (t == 0) {
        float s = 0.f;
#pragma unroll
        for (int w = 0; w < 8; w++) s += red[w];
        atomicAdd(out, s);
    }
}

// ---------------------------------------------------------------------------
extern "C" void kernel_launch(void* const* d_in, const int* in_sizes, int n_in,
                              void* d_out, int out_size) {
    const float* pred  = (const float*)d_in[0];
    const int*   label = (const int*)d_in[1];
    float* out = (float*)d_out;

    const int smem_bytes = (16384 + 256) * 4;     // 66560
    cudaFuncSetAttribute(kchan, cudaFuncAttributeMaxDynamicSharedMemorySize, smem_bytes);

    kprep<<<256, 256>>>(label, pred, out, out_size);

    // fork: kchan FIRST (backbone), then kpoint trickles on low-prio stream
    cudaEventRecord(g_evFork, 0);
    cudaStreamWaitEvent(g_s2, g_evFork, 0);
    kchan<<<NCHH, 256, smem_bytes>>>(pred);
    kpoint<<<NPT, 256, 0, g_s2>>>(pred);
    cudaEventRecord(g_evJoin, g_s2);
    cudaStreamWaitEvent(0, g_evJoin, 0);

    kfin<<<dim3(32, Bb), 256>>>(out);
}

// round 16
// speedup vs baseline: 1.2431x; 1.2431x over previous
#include <cuda_runtime.h>
#include <math.h>

#define Bb 8
#define Cc 128
#define Nn 65536
#define Ll 64
#define NPT 1024                  // point blocks (512 pts each)
#define NCHH (Bb * Cc * 2)        // 2048 channel half-blocks
#define NBLK (NPT + NCHH)         // 3072

// Scratch in device globals. g_censum zeroed by klab then atomically
// accumulated (exactly 2 adds per cell -> commutative -> deterministic).
__device__ unsigned int g_lab8[Bb * Nn / 4];     // packed uint8 labels
__device__ float g_censum[Bb * Ll * Cc];
__device__ float g_vpart[NPT * Ll];
__device__ float g_cpart[NPT * Ll];

// float4/float2 loads with L2 evict-last via cache-policy hint: pred lines
// are touched exactly twice (point + channel pass); retention makes the 2nd
// touch an L2 hit (measured R13: DRAM traffic ~274MB ~= single read).
__device__ __forceinline__ float4 ldg_el(const float4* p) {
    float4 v;
    unsigned long long pol;
    asm volatile("createpolicy.fractional.L2::evict_last.b64 %0, 1.0;" : "=l"(pol));
    asm volatile("ld.global.nc.L2::cache_hint.v4.f32 {%0,%1,%2,%3}, [%4], %5;"
                 : "=f"(v.x), "=f"(v.y), "=f"(v.z), "=f"(v.w)
                 : "l"(p), "l"(pol));
    return v;
}
__device__ __forceinline__ float2 ldg_el2(const float2* p) {
    float2 v;
    unsigned long long pol;
    asm volatile("createpolicy.fractional.L2::evict_last.b64 %0, 1.0;" : "=l"(pol));
    asm volatile("ld.global.nc.L2::cache_hint.v2.f32 {%0,%1}, [%2], %3;"
                 : "=f"(v.x), "=f"(v.y) : "l"(p), "l"(pol));
    return v;
}

// ---------------------------------------------------------------------------
// klab: pack labels to uint8x4, zero censum + out, and prefetch the first
// 16 MB of pred into L2 (hides under the first-kernel clock ramp).
// ---------------------------------------------------------------------------
__global__ __launch_bounds__(256) void klab(const int* __restrict__ label,
                                            const float* __restrict__ pred,
                                            float* __restrict__ out, int out_size) {
    const int t = blockIdx.x * 256 + threadIdx.x;      // 65536 threads
    const int4* l4 = (const int4*)label;
#pragma unroll
    for (int k = 0; k < 2; k++) {
        int i = t * 2 + k;
        int4 l = l4[i];
        g_lab8[i] = (unsigned)l.x | ((unsigned)l.y << 8) |
                    ((unsigned)l.z << 16) | ((unsigned)l.w << 24);
    }
    g_censum[t] = 0.0f;
    if (t < out_size) out[t] = 0.0f;
    asm volatile("prefetch.global.L2 [%0];" :: "l"(pred + (size_t)t * 64));
}

// ---------------------------------------------------------------------------
// kboth: merged grid, 1 point : 2 channel-half interleave (bid%3), batch-
// aligned so both passes touch the same batch within one L2 window.
// ---------------------------------------------------------------------------
__global__ __launch_bounds__(256, 3) void kboth(const float* __restrict__ pred) {
    extern __shared__ float sm[];
    const int t = threadIdx.x;
    const int bid = blockIdx.x;
    const int g3 = bid / 3, r3 = bid - 3 * g3;

    if (r3 == 0) {
        // ================= point pass (512 pts) =================
        const int b = g3 >> 7, ps = g3 & 127;
        const int n0 = ps * 512;                        // 256 thr x 2 pts
        const float2* p2 = (const float2*)(pred + (size_t)b * Cc * Nn + n0);

        float s1x = 0.f, s1y = 0.f, s2x = 0.f, s2y = 0.f;
        float2 VA[8], VB[8];
#pragma unroll
        for (int k = 0; k < 8; k++) VA[k] = ldg_el2(p2 + (size_t)k * (Nn / 2) + t);

#pragma unroll 1
        for (int cg = 0; cg < 16; cg += 2) {
#pragma unroll
            for (int k = 0; k < 8; k++)
                VB[k] = ldg_el2(p2 + (size_t)((cg + 1) * 8 + k) * (Nn / 2) + t);
#pragma unroll
            for (int k = 0; k < 8; k++) {
                s1x += VA[k].x; s2x = fmaf(VA[k].x, VA[k].x, s2x);
                s1y += VA[k].y; s2y = fmaf(VA[k].y, VA[k].y, s2y);
            }
            if (cg + 2 < 16) {
#pragma unroll
                for (int k = 0; k < 8; k++)
                    VA[k] = ldg_el2(p2 + (size_t)((cg + 2) * 8 + k) * (Nn / 2) + t);
            }
#pragma unroll
            for (int k = 0; k < 8; k++) {
                s1x += VB[k].x; s2x = fmaf(VB[k].x, VB[k].x, s2x);
                s1y += VB[k].y; s2y = fmaf(VB[k].y, VB[k].y, s2y);
            }
        }
        unsigned w = g_lab8[b * (Nn / 4) + (n0 >> 2) + (t >> 1)];
        int sh = (t & 1) * 16;
        int l0 = (w >> sh) & 255, l1 = (w >> (sh + 8)) & 255;

        float* vbin = sm;            // [64]
        float* cbin = sm + 64;       // [64]
        if (t < Ll) { vbin[t] = 0.f; cbin[t] = 0.f; }
        __syncthreads();
        {
            float pn2, d, v;
            pn2 = fmaxf(s2x - s1x * s1x * (1.0f / Cc), 0.f);
            d = sqrtf(pn2) - 0.5f; v = (d > 0.f) ? d * d : 0.f;
            atomicAdd(&vbin[l0], v); atomicAdd(&cbin[l0], 1.f);
            pn2 = fmaxf(s2y - s1y * s1y * (1.0f / Cc), 0.f);
            d = sqrtf(pn2) - 0.5f; v = (d > 0.f) ? d * d : 0.f;
            atomicAdd(&vbin[l1], v); atomicAdd(&cbin[l1], 1.f);
        }
        __syncthreads();
        if (t < Ll) {
            g_vpart[g3 * Ll + t] = vbin[t];
            g_cpart[g3 * Ll + t] = cbin[t];
        }
    } else {
        // ================= channel half-pass (32768 pts) =================
        const int id = 2 * g3 + (r3 - 1);               // 0..2047
        const int b = id >> 8;
        const int rem = id & 255;
        const int c = rem >> 1, half = rem & 1;
        float* acc = sm;             // [2 copies][64 labels][128 slots]
        float* red = sm + 16384;     // [256]

        {   // float4 zeroing
            float4* az = (float4*)acc;
            float4 z = make_float4(0.f, 0.f, 0.f, 0.f);
#pragma unroll
            for (int i = 0; i < 16; i++) az[i * 256 + t] = z;
        }
        __syncthreads();

        const float4* p4 = (const float4*)(pred + (size_t)b * Cc * Nn + (size_t)c * Nn)
                           + half * 8192;
        const unsigned* lp = g_lab8 + b * (Nn / 4) + half * 8192;
        float* ap = acc + (t >> 7) * 8192 + (t & 127);  // private slot column

        float4 XA[4], XB[4]; unsigned LA[4], LB[4];
#pragma unroll
        for (int k = 0; k < 4; k++) { XA[k] = ldg_el(p4 + k * 256 + t); LA[k] = lp[k * 256 + t]; }

#pragma unroll 1
        for (int s = 0; s < 8; s += 2) {                // 8192 float4 total
#pragma unroll
            for (int k = 0; k < 4; k++) {
                int idx = ((s + 1) * 4 + k) * 256 + t;
                XB[k] = ldg_el(p4 + idx); LB[k] = lp[idx];
            }
#pragma unroll
            for (int k = 0; k < 4; k++) {
                ap[(LA[k] & 255) * 128]         += XA[k].x;   // bank=slot%32: clean
                ap[((LA[k] >> 8) & 255) * 128]  += XA[k].y;
                ap[((LA[k] >> 16) & 255) * 128] += XA[k].z;
                ap[(LA[k] >> 24) * 128]         += XA[k].w;
            }
            if (s + 2 < 8) {
#pragma unroll
                for (int k = 0; k < 4; k++) {
                    int idx = ((s + 2) * 4 + k) * 256 + t;
                    XA[k] = ldg_el(p4 + idx); LA[k] = lp[idx];
                }
            }
#pragma unroll
            for (int k = 0; k < 4; k++) {
                ap[(LB[k] & 255) * 128]         += XB[k].x;
                ap[((LB[k] >> 8) & 255) * 128]  += XB[k].y;
                ap[((LB[k] >> 16) & 255) * 128] += XB[k].z;
                ap[(LB[k] >> 24) * 128]         += XB[k].w;
            }
        }
        __syncthreads();

        {   // float4 diagonal reduce
            const int l = t & 63, q = t >> 6;
            const float4* a4 = (const float4*)acc;
            float s = 0.f;
#pragma unroll
            for (int jj = 0; jj < 8; jj++) {
                int j4 = (q * 8 + jj + l) & 31;
                float4 v0 = a4[l * 32 + j4];
                float4 v1 = a4[2048 + l * 32 + j4];
                s += (v0.x + v0.y + v0.z + v0.w) + (v1.x + v1.y + v1.z + v1.w);
            }
            red[t] = s;
        }
        __syncthreads();
        if (t < Ll)                    // 2 adds/cell: commutative -> deterministic
            atomicAdd(&g_censum[((size_t)b * Ll + t) * Cc + c],
                      red[t] + red[t + 64] + red[t + 128] + red[t + 192]);
    }
}

// ---------------------------------------------------------------------------
// kfin: merged finalize at grid (16, Bb) — measured-faster shape (R8: 7.1us
// vs 11.4us at (32,Bb)). Block q covers d in [q*8, q*8+8), 4 accumulators.
// ---------------------------------------------------------------------------
__global__ __launch_bounds__(256) void kfin(float* __restrict__ out) {
    const int q = blockIdx.x, b = blockIdx.y, t = threadIdx.x;
    __shared__ float cen[Ll][Cc];    // 32 KB
    __shared__ float ps[256];
    __shared__ float qs[256];
    __shared__ float icnt[Ll];
    __shared__ float vc[Ll];
    __shared__ float sq[Cc];
    __shared__ float red[8];

    {   // counts + vsums: 32 point-blocks per thread (128 per batch)
        const int l = t & 63, sg = t >> 6;
        float cs = 0.f, vv = 0.f;
#pragma unroll 4
        for (int k = 0; k < 32; k++) {
            int idx = (b * 128 + sg * 32 + k) * Ll + l;
            cs += g_cpart[idx];
            vv += g_vpart[idx];
        }
        ps[t] = cs; qs[t] = vv;
    }
    __syncthreads();
    if (t < Ll) {
        float ctot = ps[t] + ps[t + 64] + ps[t + 128] + ps[t + 192];
        icnt[t] = 1.0f / ctot;
        vc[t] = (qs[t] + qs[t + 64] + qs[t + 128] + qs[t + 192]) / ctot;
    }
    __syncthreads();

    {   // normalized centers (float4: 4 consecutive c share one l)
        const float4* src = (const float4*)(g_censum + (size_t)b * Ll * Cc);
        float4* dst = (float4*)&cen[0][0];
#pragma unroll
        for (int i = 0; i < 8; i++) {
            int idx = i * 256 + t;
            float ic = icnt[idx >> 5];
            float4 v = src[idx];
            v.x *= ic; v.y *= ic; v.z *= ic; v.w *= ic;
            dst[idx] = v;
        }
    }
    __syncthreads();

    {   // sqn: half-column per thread then combine
        const int c = t & 127, h = t >> 7;
        float s = 0.f;
#pragma unroll 8
        for (int l = h * 32; l < h * 32 + 32; l++) { float v = cen[l][c]; s = fmaf(v, v, s); }
        ps[t] = s;
    }
    __syncthreads();
    if (t < Cc) sq[t] = ps[t] + ps[t + 128];
    __syncthreads();

    // gram slice: 4 accumulators per thread (measured-faster R8 shape)
    const int cc = t & 127;
    const int d0 = q * 8 + (t >> 7) * 4;
    float g0 = 0.f, g1 = 0.f, g2 = 0.f, g3 = 0.f;
#pragma unroll 8
    for (int l = 0; l < Ll; l++) {
        float a = cen[l][cc];
        g0 = fmaf(a, cen[l][d0 + 0], g0);
        g1 = fmaf(a, cen[l][d0 + 1], g1);
        g2 = fmaf(a, cen[l][d0 + 2], g2);
        g3 = fmaf(a, cen[l][d0 + 3], g3);
    }
    float gg[4] = {g0, g1, g2, g3};
    float local = 0.f;
#pragma unroll
    for (int j = 0; j < 4; j++) {
        float sqd = fmaxf(sq[cc] + sq[d0 + j] - 2.0f * gg[j], 0.f);
        float dist = (sqd > 0.f) ? sqrtf(sqd) : 0.f;
        float h = fmaxf(3.0f - dist, 0.f);        // 2*D_DIST
        local = fmaf(h, h, local);
    }
    local *= (1.0f / 8064.0f);                    // P_DIST / (2*L*(L-1))

    if (q == 0 && t < Cc) {
        local += 0.001f * sqrtf(sq[t]) * (1.0f / 64.0f);   // l_reg
        if (t < Ll) local += vc[t] * (1.0f / 64.0f);       // var
    }

    for (int off = 16; off > 0; off >>= 1)
        local += __shfl_down_sync(0xFFFFFFFFu, local, off);
    if ((t & 31) == 0) red[t >> 5] = local;
    __syncthreads();
    if (t == 0) {
        float s = 0.f;
#pragma unroll
        for (int w = 0; w < 8; w++) s += red[w];
        atomicAdd(out, s);
    }
}

// ---------------------------------------------------------------------------
extern "C" void kernel_launch(void* const* d_in, const int* in_sizes, int n_in,
                              void* d_out, int out_size) {
    const float* pred  = (const float*)d_in[0];
    const int*   label = (const int*)d_in[1];
    float* out = (float*)d_out;

    const int smem_bytes = (16384 + 256) * 4;     // 66560
    cudaFuncSetAttribute(kboth, cudaFuncAttributeMaxDynamicSharedMemorySize, smem_bytes);

    klab<<<256, 256>>>(label, pred, out, out_size);
    kboth<<<NBLK, 256, smem_bytes>>>(pred);
    kfin<<<dim3(16, Bb), 256>>>(out);
}